// round 1
// baseline (speedup 1.0000x reference)
#include <cuda_runtime.h>
#include <math_constants.h>

#define NTR 8192
#define NT  8192
#define DIN 1024
#define LD  64
#define DY  128

#define BM 64
#define BN 128

#define SQ_STRIDE 68
#define SK_STRIDE 132
#define SP_STRIDE 132

// scratch (static device arrays: no allocations allowed)
__device__ float g_Q[(size_t)NT * LD];
__device__ float g_K[(size_t)NTR * LD];
__device__ float g_muA[LD];

// ---------------------------------------------------------------------------
// Projection: C[8192,64] = X[8192,1024] @ A[1024,64]
// blocks 0..63  -> xtr -> g_K ; blocks 64..127 -> xt -> g_Q
// BMp=128 rows/block, full N=64, BK=32, 256 threads, 8x4 micro-tile.
// ---------------------------------------------------------------------------
__global__ __launch_bounds__(256) void proj_kernel(const float* __restrict__ xtr,
                                                   const float* __restrict__ xt,
                                                   const float* __restrict__ A) {
    __shared__ float sX[32 * 132];  // transposed [k][row], padded
    __shared__ float sA[32 * 64];   // [k][l]

    const bool isQ = (blockIdx.x >= 64);
    const float* __restrict__ X = isQ ? xt : xtr;
    float* C = isQ ? g_Q : g_K;
    const int mbase = (blockIdx.x & 63) * 128;
    const int ty = threadIdx.x >> 4;
    const int tx = threadIdx.x & 15;

    float acc[8][4];
#pragma unroll
    for (int i = 0; i < 8; ++i)
#pragma unroll
        for (int j = 0; j < 4; ++j) acc[i][j] = 0.0f;

    for (int k0 = 0; k0 < DIN; k0 += 32) {
        // load X tile [128 rows x 32 k] transposed into sX[k][row]
#pragma unroll
        for (int i4 = threadIdx.x; i4 < 1024; i4 += 256) {
            const int r  = i4 >> 3;
            const int kk = (i4 & 7) << 2;
            float4 v = *(const float4*)(X + (size_t)(mbase + r) * DIN + k0 + kk);
            sX[(kk + 0) * 132 + r] = v.x;
            sX[(kk + 1) * 132 + r] = v.y;
            sX[(kk + 2) * 132 + r] = v.z;
            sX[(kk + 3) * 132 + r] = v.w;
        }
        // load A tile [32 x 64]
#pragma unroll
        for (int i4 = threadIdx.x; i4 < 512; i4 += 256) {
            ((float4*)sA)[i4] =
                *(const float4*)(A + (size_t)(k0 + (i4 >> 4)) * LD + ((i4 & 15) << 2));
        }
        __syncthreads();

#pragma unroll
        for (int kk = 0; kk < 32; ++kk) {
            float xr[8], ar[4];
            *(float4*)&xr[0] = *(const float4*)(sX + kk * 132 + 8 * ty);
            *(float4*)&xr[4] = *(const float4*)(sX + kk * 132 + 8 * ty + 4);
            *(float4*)&ar[0] = *(const float4*)(sA + kk * 64 + 4 * tx);
#pragma unroll
            for (int i = 0; i < 8; ++i)
#pragma unroll
                for (int j = 0; j < 4; ++j)
                    acc[i][j] = fmaf(xr[i], ar[j], acc[i][j]);
        }
        __syncthreads();
    }

#pragma unroll
    for (int i = 0; i < 8; ++i) {
        *(float4*)(C + (size_t)(mbase + 8 * ty + i) * LD + 4 * tx) =
            make_float4(acc[i][0], acc[i][1], acc[i][2], acc[i][3]);
    }
}

// ---------------------------------------------------------------------------
// muA[l] = mean over rows of g_K[.,l]   (deterministic tree reduce, no atomics)
// ---------------------------------------------------------------------------
__global__ __launch_bounds__(256) void colmean_kernel() {
    __shared__ float red[256];
    const int l = blockIdx.x;
    float s = 0.0f;
    for (int r = threadIdx.x; r < NTR; r += 256) s += g_K[(size_t)r * LD + l];
    red[threadIdx.x] = s;
    __syncthreads();
    for (int off = 128; off > 0; off >>= 1) {
        if (threadIdx.x < off) red[threadIdx.x] += red[threadIdx.x + off];
        __syncthreads();
    }
    if (threadIdx.x == 0) g_muA[l] = red[0] * (1.0f / (float)NTR);
}

// ---------------------------------------------------------------------------
// Flash attention, fp32. BM=64 queries/block, BN=128 keys/iter, 256 threads.
// Thread (ty,tx) in 16x16 grid: owns S/O rows 4*ty+i, cols {4*tx+j, 64+4*tx+j}.
// ---------------------------------------------------------------------------
extern __shared__ float fsmem[];

__global__ __launch_bounds__(256) void flash_kernel(const float* __restrict__ ytr,
                                                    float* __restrict__ out) {
    float* sQ = fsmem;                    // [64 dims][68]  (col = query row)
    float* sK = sQ + 64 * SQ_STRIDE;      // [64 dims][132] (col = key row)
    float* sV = sK + 64 * SK_STRIDE;      // [128][128]
    float* sP = sV + 128 * 128;           // [64 rows][132]

    const int tid = threadIdx.x;
    const int ty = tid >> 4;
    const int tx = tid & 15;
    const int qbase = blockIdx.x * BM;

    // load Q tile once, centered, transposed to [dim][row]
#pragma unroll
    for (int i4 = tid; i4 < BM * LD / 4; i4 += 256) {
        const int r  = i4 >> 4;
        const int l4 = (i4 & 15) << 2;
        float4 v = *(const float4*)(g_Q + (size_t)(qbase + r) * LD + l4);
        sQ[(l4 + 0) * SQ_STRIDE + r] = v.x - g_muA[l4 + 0];
        sQ[(l4 + 1) * SQ_STRIDE + r] = v.y - g_muA[l4 + 1];
        sQ[(l4 + 2) * SQ_STRIDE + r] = v.z - g_muA[l4 + 2];
        sQ[(l4 + 3) * SQ_STRIDE + r] = v.w - g_muA[l4 + 3];
    }

    float o[4][8];
    float m[4], lsum[4];
#pragma unroll
    for (int i = 0; i < 4; ++i) {
        m[i] = -CUDART_INF_F;
        lsum[i] = 0.0f;
#pragma unroll
        for (int j = 0; j < 8; ++j) o[i][j] = 0.0f;
    }

    for (int jt = 0; jt < NTR / BN; ++jt) {
        const int kb = jt * BN;

        // K tile, centered, transposed to [dim][key]
#pragma unroll
        for (int i4 = tid; i4 < BN * LD / 4; i4 += 256) {
            const int c  = i4 >> 4;
            const int l4 = (i4 & 15) << 2;
            float4 v = *(const float4*)(g_K + (size_t)(kb + c) * LD + l4);
            sK[(l4 + 0) * SK_STRIDE + c] = v.x - g_muA[l4 + 0];
            sK[(l4 + 1) * SK_STRIDE + c] = v.y - g_muA[l4 + 1];
            sK[(l4 + 2) * SK_STRIDE + c] = v.z - g_muA[l4 + 2];
            sK[(l4 + 3) * SK_STRIDE + c] = v.w - g_muA[l4 + 3];
        }
        // V tile (straight copy)
#pragma unroll
        for (int i4 = tid; i4 < BN * DY / 4; i4 += 256) {
            ((float4*)sV)[i4] = ((const float4*)(ytr + (size_t)kb * DY))[i4];
        }
        __syncthreads();

        // S = Q K^T  (4x8 per thread)
        float s[4][8];
#pragma unroll
        for (int i = 0; i < 4; ++i)
#pragma unroll
            for (int j = 0; j < 8; ++j) s[i][j] = 0.0f;

#pragma unroll 8
        for (int l2 = 0; l2 < LD; ++l2) {
            float qa[4], ka[8];
            *(float4*)&qa[0] = *(const float4*)(sQ + l2 * SQ_STRIDE + 4 * ty);
            *(float4*)&ka[0] = *(const float4*)(sK + l2 * SK_STRIDE + 4 * tx);
            *(float4*)&ka[4] = *(const float4*)(sK + l2 * SK_STRIDE + 64 + 4 * tx);
#pragma unroll
            for (int i = 0; i < 4; ++i)
#pragma unroll
                for (int j = 0; j < 8; ++j)
                    s[i][j] = fmaf(qa[i], ka[j], s[i][j]);
        }

        // online softmax; row r = 4*ty+i spans the 16 tx lanes of this half-warp
#pragma unroll
        for (int i = 0; i < 4; ++i) {
            float mx = s[i][0];
#pragma unroll
            for (int j = 1; j < 8; ++j) mx = fmaxf(mx, s[i][j]);
#pragma unroll
            for (int off = 8; off >= 1; off >>= 1)
                mx = fmaxf(mx, __shfl_xor_sync(0xffffffffu, mx, off));
            const float mnew = fmaxf(m[i], mx);
            const float corr = __expf(m[i] - mnew);
            float rs = 0.0f;
#pragma unroll
            for (int j = 0; j < 8; ++j) {
                const float p = __expf(s[i][j] - mnew);
                s[i][j] = p;
                rs += p;
            }
#pragma unroll
            for (int off = 8; off >= 1; off >>= 1)
                rs += __shfl_xor_sync(0xffffffffu, rs, off);
            lsum[i] = lsum[i] * corr + rs;
            m[i] = mnew;
#pragma unroll
            for (int j = 0; j < 8; ++j) o[i][j] *= corr;

            *(float4*)(sP + (4 * ty + i) * SP_STRIDE + 4 * tx) =
                make_float4(s[i][0], s[i][1], s[i][2], s[i][3]);
            *(float4*)(sP + (4 * ty + i) * SP_STRIDE + 64 + 4 * tx) =
                make_float4(s[i][4], s[i][5], s[i][6], s[i][7]);
        }
        __syncthreads();

        // O += P V
#pragma unroll 4
        for (int n0 = 0; n0 < BN; n0 += 4) {
            float pr[4][4];
#pragma unroll
            for (int i = 0; i < 4; ++i)
                *(float4*)pr[i] = *(const float4*)(sP + (4 * ty + i) * SP_STRIDE + n0);
#pragma unroll
            for (int jj = 0; jj < 4; ++jj) {
                float va[8];
                *(float4*)&va[0] = *(const float4*)(sV + (n0 + jj) * DY + 4 * tx);
                *(float4*)&va[4] = *(const float4*)(sV + (n0 + jj) * DY + 64 + 4 * tx);
#pragma unroll
                for (int i = 0; i < 4; ++i)
#pragma unroll
                    for (int j = 0; j < 8; ++j)
                        o[i][j] = fmaf(pr[i][jj], va[j], o[i][j]);
            }
        }
        __syncthreads();
    }

    // epilogue
#pragma unroll
    for (int i = 0; i < 4; ++i) {
        const float inv = 1.0f / lsum[i];
        float* orow = out + (size_t)(qbase + 4 * ty + i) * DY;
        *(float4*)(orow + 4 * tx) =
            make_float4(o[i][0] * inv, o[i][1] * inv, o[i][2] * inv, o[i][3] * inv);
        *(float4*)(orow + 64 + 4 * tx) =
            make_float4(o[i][4] * inv, o[i][5] * inv, o[i][6] * inv, o[i][7] * inv);
    }
}

// ---------------------------------------------------------------------------
extern "C" void kernel_launch(void* const* d_in, const int* in_sizes, int n_in,
                              void* d_out, int out_size) {
    const float* xtr = (const float*)d_in[0];  // [8192,1024]
    const float* ytr = (const float*)d_in[1];  // [8192,128]
    const float* xt  = (const float*)d_in[2];  // [8192,1024]
    const float* A   = (const float*)d_in[3];  // [1024,64]
    float* out = (float*)d_out;                // [8192,128] fp32

    const int smem_bytes =
        (64 * SQ_STRIDE + 64 * SK_STRIDE + 128 * 128 + 64 * SP_STRIDE) * (int)sizeof(float);
    cudaFuncSetAttribute(flash_kernel, cudaFuncAttributeMaxDynamicSharedMemorySize,
                         smem_bytes);

    proj_kernel<<<128, 256>>>(xtr, xt, A);
    colmean_kernel<<<64, 256>>>();
    flash_kernel<<<128, 256, smem_bytes>>>(ytr, out);
}

// round 4
// speedup vs baseline: 2.9483x; 2.9483x over previous
#include <cuda_runtime.h>
#include <cuda_bf16.h>
#include <cstdint>

#define NTR 8192
#define NT  8192
#define DIN 1024
#define LD  64
#define DY  128

// ---------------------------------------------------------------------------
// device scratch (no allocations allowed)
// ---------------------------------------------------------------------------
__device__ float g_Q[(size_t)NT * LD];
__device__ float g_K[(size_t)NTR * LD];
__device__ float g_muA[LD];
__device__ __nv_bfloat16 g_Qh[(size_t)NT * LD];
__device__ __nv_bfloat16 g_Ql[(size_t)NT * LD];
__device__ __nv_bfloat16 g_Kh[(size_t)NTR * LD];
__device__ __nv_bfloat16 g_Kl[(size_t)NTR * LD];
__device__ __nv_bfloat16 g_Vh[(size_t)NTR * DY];
__device__ __nv_bfloat16 g_Vl[(size_t)NTR * DY];
__device__ float g_Opart[2 * (size_t)NT * DY];
__device__ float g_lpart[2 * (size_t)NT];

// ---------------------------------------------------------------------------
// helpers (portable PTX only: sm_80-level mma/ldmatrix/cp.async)
// ---------------------------------------------------------------------------
__device__ __forceinline__ uint32_t smem_u32(const void* p) {
    uint32_t a;
    asm("{ .reg .u64 t; cvta.to.shared.u64 t, %1; cvt.u32.u64 %0, t; }"
        : "=r"(a) : "l"(p));
    return a;
}

__device__ __forceinline__ void cp16(uint32_t dst, const void* src) {
    asm volatile("cp.async.cg.shared.global [%0], [%1], 16;"
                 :: "r"(dst), "l"(src));
}
#define CP_COMMIT asm volatile("cp.async.commit_group;" ::: "memory")
#define CP_WAIT0  asm volatile("cp.async.wait_group 0;" ::: "memory")

__device__ __forceinline__ void ldsm_x4(uint32_t* r, uint32_t a) {
    asm volatile("ldmatrix.sync.aligned.m8n8.x4.shared.b16 {%0,%1,%2,%3}, [%4];"
                 : "=r"(r[0]), "=r"(r[1]), "=r"(r[2]), "=r"(r[3]) : "r"(a));
}
// non-trans x2: for K (B[k=dim][n=key] with K stored [key][dim])
__device__ __forceinline__ void ldsm_x2(uint32_t& r0, uint32_t& r1, uint32_t a) {
    asm volatile("ldmatrix.sync.aligned.m8n8.x2.shared.b16 {%0,%1}, [%2];"
                 : "=r"(r0), "=r"(r1) : "r"(a));
}
// trans x2: for V (B[k=key][n=dy] with V stored [key][dy])
__device__ __forceinline__ void ldsm_x2t(uint32_t& r0, uint32_t& r1, uint32_t a) {
    asm volatile("ldmatrix.sync.aligned.m8n8.x2.trans.shared.b16 {%0,%1}, [%2];"
                 : "=r"(r0), "=r"(r1) : "r"(a));
}
__device__ __forceinline__ void mma_bf16(float* c, const uint32_t* a,
                                         uint32_t b0, uint32_t b1) {
    asm volatile(
        "mma.sync.aligned.m16n8k16.row.col.f32.bf16.bf16.f32 "
        "{%0,%1,%2,%3}, {%4,%5,%6,%7}, {%8,%9}, {%0,%1,%2,%3};"
        : "+f"(c[0]), "+f"(c[1]), "+f"(c[2]), "+f"(c[3])
        : "r"(a[0]), "r"(a[1]), "r"(a[2]), "r"(a[3]), "r"(b0), "r"(b1));
}

__device__ __forceinline__ uint32_t pack_bf16(float a, float b) {
    const unsigned short ha = __bfloat16_as_ushort(__float2bfloat16(a));
    const unsigned short hb = __bfloat16_as_ushort(__float2bfloat16(b));
    return (uint32_t)ha | ((uint32_t)hb << 16);
}
__device__ __forceinline__ float bf_hi_res(float v, float& res) {
    const __nv_bfloat16 h = __float2bfloat16(v);
    res = v - __bfloat162float(h);
    return __bfloat162float(h);
}

// ---------------------------------------------------------------------------
// Projection: C[8192,64] = X[8192,1024] @ A[1024,64]; 256 blocks x 64 rows
// ---------------------------------------------------------------------------
__global__ __launch_bounds__(256) void proj_kernel(const float* __restrict__ xtr,
                                                   const float* __restrict__ xt,
                                                   const float* __restrict__ A) {
    __shared__ float sX[32 * 68];
    __shared__ float sA[32 * 64];

    const bool isQ = (blockIdx.x >= 128);
    const float* __restrict__ X = isQ ? xt : xtr;
    float* C = isQ ? g_Q : g_K;
    const int mbase = (blockIdx.x & 127) * 64;
    const int ty = threadIdx.x >> 4;
    const int tx = threadIdx.x & 15;

    float acc[4][4];
#pragma unroll
    for (int i = 0; i < 4; ++i)
#pragma unroll
        for (int j = 0; j < 4; ++j) acc[i][j] = 0.0f;

    for (int k0 = 0; k0 < DIN; k0 += 32) {
#pragma unroll
        for (int i4 = threadIdx.x; i4 < 512; i4 += 256) {
            const int r  = i4 >> 3;
            const int kk = (i4 & 7) << 2;
            float4 v = *(const float4*)(X + (size_t)(mbase + r) * DIN + k0 + kk);
            sX[(kk + 0) * 68 + r] = v.x;
            sX[(kk + 1) * 68 + r] = v.y;
            sX[(kk + 2) * 68 + r] = v.z;
            sX[(kk + 3) * 68 + r] = v.w;
        }
#pragma unroll
        for (int i4 = threadIdx.x; i4 < 512; i4 += 256) {
            ((float4*)sA)[i4] =
                *(const float4*)(A + (size_t)(k0 + (i4 >> 4)) * LD + ((i4 & 15) << 2));
        }
        __syncthreads();

#pragma unroll
        for (int kk = 0; kk < 32; ++kk) {
            float xr[4], ar[4];
            *(float4*)&xr[0] = *(const float4*)(sX + kk * 68 + 4 * ty);
            *(float4*)&ar[0] = *(const float4*)(sA + kk * 64 + 4 * tx);
#pragma unroll
            for (int i = 0; i < 4; ++i)
#pragma unroll
                for (int j = 0; j < 4; ++j)
                    acc[i][j] = fmaf(xr[i], ar[j], acc[i][j]);
        }
        __syncthreads();
    }

#pragma unroll
    for (int i = 0; i < 4; ++i) {
        *(float4*)(C + (size_t)(mbase + 4 * ty + i) * LD + 4 * tx) =
            make_float4(acc[i][0], acc[i][1], acc[i][2], acc[i][3]);
    }
}

// ---------------------------------------------------------------------------
__global__ __launch_bounds__(256) void colmean_kernel() {
    __shared__ float red[256];
    const int l = blockIdx.x;
    float s = 0.0f;
    for (int r = threadIdx.x; r < NTR; r += 256) s += g_K[(size_t)r * LD + l];
    red[threadIdx.x] = s;
    __syncthreads();
    for (int off = 128; off > 0; off >>= 1) {
        if (threadIdx.x < off) red[threadIdx.x] += red[threadIdx.x + off];
        __syncthreads();
    }
    if (threadIdx.x == 0) g_muA[l] = red[0] * (1.0f / (float)NTR);
}

// ---------------------------------------------------------------------------
// center + bf16 split of Q/K
// ---------------------------------------------------------------------------
__global__ __launch_bounds__(256) void split_qk_kernel() {
    int i = blockIdx.x * 256 + threadIdx.x;      // 0..262143 float4 elems
    const bool isQ = (i >= 131072);
    const float* src = isQ ? g_Q : g_K;
    __nv_bfloat16* dh = isQ ? g_Qh : g_Kh;
    __nv_bfloat16* dl = isQ ? g_Ql : g_Kl;
    const int j = isQ ? i - 131072 : i;
    float4 v = ((const float4*)src)[j];
    const int l = (j * 4) & 63;
    v.x -= g_muA[l + 0];
    v.y -= g_muA[l + 1];
    v.z -= g_muA[l + 2];
    v.w -= g_muA[l + 3];
    float r0, r1, r2, r3;
    const float h0 = bf_hi_res(v.x, r0), h1 = bf_hi_res(v.y, r1);
    const float h2 = bf_hi_res(v.z, r2), h3 = bf_hi_res(v.w, r3);
    uint2 ph, pl;
    ph.x = pack_bf16(h0, h1); ph.y = pack_bf16(h2, h3);
    pl.x = pack_bf16(r0, r1); pl.y = pack_bf16(r2, r3);
    ((uint2*)dh)[j] = ph;
    ((uint2*)dl)[j] = pl;
}

// ---------------------------------------------------------------------------
// V split (keeps [key][dy] layout): ytr [8192,128] f32 -> Vh/Vl bf16
// ---------------------------------------------------------------------------
__global__ __launch_bounds__(256) void vsplit_kernel(const float* __restrict__ ytr) {
    const int i = blockIdx.x * 256 + threadIdx.x;  // float4 idx, 262144 total
    float4 v = ((const float4*)ytr)[i];
    float r0, r1, r2, r3;
    const float h0 = bf_hi_res(v.x, r0), h1 = bf_hi_res(v.y, r1);
    const float h2 = bf_hi_res(v.z, r2), h3 = bf_hi_res(v.w, r3);
    uint2 ph, pl;
    ph.x = pack_bf16(h0, h1); ph.y = pack_bf16(h2, h3);
    pl.x = pack_bf16(r0, r1); pl.y = pack_bf16(r2, r3);
    ((uint2*)g_Vh)[i] = ph;
    ((uint2*)g_Vl)[i] = pl;
}

// ---------------------------------------------------------------------------
// flash kernel: mma.sync bf16, 128 CTAs = 64 qblks x 2 key-halves,
// 256 threads = 8 warps, each warp owns 16 query rows.
// smem: Qh/Ql 16KB each, Kh/Kl 16KB each, Vh/Vl 32KB each = 128KB
// ---------------------------------------------------------------------------
#define FB_QH 0
#define FB_QL 16384
#define FB_KH 32768
#define FB_KL 49152
#define FB_VH 65536
#define FB_VL 98304
#define FSM_BYTES 131072

extern __shared__ char fsm[];

__global__ __launch_bounds__(256) void flash_mma_kernel() {
    const int tid = threadIdx.x;
    const int wid = tid >> 5;
    const int lane = tid & 31;
    const int g = lane >> 2;        // accum row group
    const int t = lane & 3;         // tid in group
    const int qblk = blockIdx.x >> 1;
    const int half = blockIdx.x & 1;
    const int qbase = qblk * 128;
    const int wr = wid * 16;        // warp's query-row base within tile
    const uint32_t sb = smem_u32(fsm);

    // ---- Q tile load (once): [128 rows][64 dims] hi+lo, swizzled 128B rows
    for (int c = tid; c < 1024; c += 256) {
        const int row = c >> 3, dc = c & 7;
        const uint32_t dst = sb + FB_QH + row * 128 + ((dc ^ (row & 7)) << 4);
        const size_t gq = ((size_t)(qbase + row) << 6) + dc * 8;
        cp16(dst, g_Qh + gq);
        cp16(dst + (FB_QL - FB_QH), g_Ql + gq);
    }
    CP_COMMIT;

    // per-lane ldmatrix address components
    const int l7 = lane & 7, l15 = lane & 15;
    const int ab = lane >> 3;                 // A block id 0..3
    const int arow = l7 + ((ab & 1) << 3);    // row within 16
    const int acs = ab >> 1;                  // A col-chunk select
    const int kcb = (lane >> 3) & 1;          // K/B second-chunk bit
    const uint32_t qa_base = sb + FB_QH + (uint32_t)(wr + arow) * 128;
    const uint32_t va_base = sb + FB_VH + (uint32_t)l15 * 256;

    float oacc[16][4];
#pragma unroll
    for (int n = 0; n < 16; ++n)
#pragma unroll
        for (int j = 0; j < 4; ++j) oacc[n][j] = 0.0f;
    float rlo = 0.0f, rhi = 0.0f;

    CP_WAIT0;
    __syncthreads();

    for (int jt = 0; jt < 32; ++jt) {
        const int kb = (half * 32 + jt) * 128;

        // ---- K tile: [128 keys][64 dims] hi+lo
        for (int c = tid; c < 1024; c += 256) {
            const int key = c >> 3, dc = c & 7;
            const uint32_t dst = sb + FB_KH + key * 128 + ((dc ^ (key & 7)) << 4);
            const size_t gk = ((size_t)(kb + key) << 6) + dc * 8;
            cp16(dst, g_Kh + gk);
            cp16(dst + (FB_KL - FB_KH), g_Kl + gk);
        }
        // ---- V tile: [128 keys][128 dy] hi+lo (256B rows)
        for (int c = tid; c < 2048; c += 256) {
            const int key = c >> 4, dc = c & 15;
            const uint32_t dst = sb + FB_VH + key * 256 + ((dc ^ (key & 7)) << 4);
            const size_t gv = ((size_t)(kb + key) << 7) + dc * 8;
            cp16(dst, g_Vh + gv);
            cp16(dst + (FB_VL - FB_VH), g_Vl + gv);
        }
        CP_COMMIT;
        CP_WAIT0;
        __syncthreads();

        // ---- S = Q K^T : 16 n-tiles x 4 k-steps, 3 split terms
        //      K fragments via NON-trans ldmatrix (B[k=dim][n=key]).
        float sacc[16][4];
#pragma unroll
        for (int n = 0; n < 16; ++n)
#pragma unroll
            for (int j = 0; j < 4; ++j) sacc[n][j] = 0.0f;

#pragma unroll
        for (int ks = 0; ks < 4; ++ks) {
            uint32_t aqh[4], aql[4];
            const uint32_t qaddr =
                qa_base + (uint32_t)((((ks << 1) + acs) ^ l7) << 4);
            ldsm_x4(aqh, qaddr);
            ldsm_x4(aql, qaddr + (FB_QL - FB_QH));
            const uint32_t ksw = (uint32_t)((((ks << 1) + kcb) ^ l7) << 4);
#pragma unroll
            for (int n = 0; n < 16; ++n) {
                const uint32_t kaddr =
                    sb + FB_KH + (uint32_t)(((n << 3) + l7) * 128) + ksw;
                uint32_t bh0, bh1, bl0, bl1;
                ldsm_x2(bh0, bh1, kaddr);
                ldsm_x2(bl0, bl1, kaddr + (FB_KL - FB_KH));
                mma_bf16(sacc[n], aqh, bh0, bh1);
                mma_bf16(sacc[n], aql, bh0, bh1);
                mma_bf16(sacc[n], aqh, bl0, bl1);
            }
        }

        // ---- P = exp(S) (no max subtraction; fp32 range is sufficient),
        //      pack in-register into A-fragments (hi + lo)
        uint32_t ph[16][2], pl[16][2];
#pragma unroll
        for (int n = 0; n < 16; ++n) {
            const float e0 = __expf(sacc[n][0]);
            const float e1 = __expf(sacc[n][1]);
            const float e2 = __expf(sacc[n][2]);
            const float e3 = __expf(sacc[n][3]);
            rlo += e0 + e1;
            rhi += e2 + e3;
            float r0, r1, r2, r3;
            const float h0 = bf_hi_res(e0, r0), h1 = bf_hi_res(e1, r1);
            const float h2 = bf_hi_res(e2, r2), h3 = bf_hi_res(e3, r3);
            ph[n][0] = pack_bf16(h0, h1);
            ph[n][1] = pack_bf16(h2, h3);
            pl[n][0] = pack_bf16(r0, r1);
            pl[n][1] = pack_bf16(r2, r3);
        }

        // ---- O += P V : 8 k-steps (16 keys) x 16 n-tiles, 3 split terms
        //      V fragments via trans ldmatrix (B[k=key][n=dy]).
#pragma unroll
        for (int s = 0; s < 8; ++s) {
            const uint32_t ah[4] = {ph[2 * s][0], ph[2 * s][1],
                                    ph[2 * s + 1][0], ph[2 * s + 1][1]};
            const uint32_t al[4] = {pl[2 * s][0], pl[2 * s][1],
                                    pl[2 * s + 1][0], pl[2 * s + 1][1]};
            const uint32_t vsb = va_base + (uint32_t)(s << 12);
#pragma unroll
            for (int n = 0; n < 16; ++n) {
                const uint32_t vaddr = vsb + (uint32_t)((n ^ l7) << 4);
                uint32_t vh0, vh1, vl0, vl1;
                ldsm_x2t(vh0, vh1, vaddr);
                ldsm_x2t(vl0, vl1, vaddr + (FB_VL - FB_VH));
                mma_bf16(oacc[n], ah, vh0, vh1);
                mma_bf16(oacc[n], al, vh0, vh1);
                mma_bf16(oacc[n], ah, vl0, vl1);
            }
        }
        __syncthreads();  // before next tile overwrites K/V
    }

    // ---- write unnormalized partial O
    float* Op = g_Opart + (size_t)half * NT * DY;
    const int row0 = qbase + wr + g;
#pragma unroll
    for (int n = 0; n < 16; ++n) {
        *(float2*)(Op + (size_t)row0 * DY + n * 8 + 2 * t) =
            make_float2(oacc[n][0], oacc[n][1]);
        *(float2*)(Op + (size_t)(row0 + 8) * DY + n * 8 + 2 * t) =
            make_float2(oacc[n][2], oacc[n][3]);
    }
    // ---- row-sum partials (reduce over the 4 lanes of each row group)
    rlo += __shfl_xor_sync(0xffffffffu, rlo, 1);
    rlo += __shfl_xor_sync(0xffffffffu, rlo, 2);
    rhi += __shfl_xor_sync(0xffffffffu, rhi, 1);
    rhi += __shfl_xor_sync(0xffffffffu, rhi, 2);
    if (t == 0) {
        g_lpart[(size_t)half * NT + row0] = rlo;
        g_lpart[(size_t)half * NT + row0 + 8] = rhi;
    }
}

// ---------------------------------------------------------------------------
// combine: out = (O0 + O1) / (l0 + l1)
// ---------------------------------------------------------------------------
__global__ __launch_bounds__(256) void combine_kernel(float* __restrict__ out) {
    const int i = blockIdx.x * 256 + threadIdx.x;  // float4 index, 262144 total
    const int r = (i * 4) >> 7;                    // query row
    const float inv = 1.0f / (g_lpart[r] + g_lpart[NT + r]);
    float4 a = ((const float4*)g_Opart)[i];
    float4 b = ((const float4*)(g_Opart + (size_t)NT * DY))[i];
    ((float4*)out)[i] = make_float4((a.x + b.x) * inv, (a.y + b.y) * inv,
                                    (a.z + b.z) * inv, (a.w + b.w) * inv);
}

// ---------------------------------------------------------------------------
extern "C" void kernel_launch(void* const* d_in, const int* in_sizes, int n_in,
                              void* d_out, int out_size) {
    const float* xtr = (const float*)d_in[0];
    const float* ytr = (const float*)d_in[1];
    const float* xt  = (const float*)d_in[2];
    const float* A   = (const float*)d_in[3];
    float* out = (float*)d_out;

    cudaFuncSetAttribute(flash_mma_kernel,
                         cudaFuncAttributeMaxDynamicSharedMemorySize, FSM_BYTES);

    proj_kernel<<<256, 256>>>(xtr, xt, A);
    colmean_kernel<<<64, 256>>>();
    split_qk_kernel<<<1024, 256>>>();
    vsplit_kernel<<<1024, 256>>>(ytr);
    flash_mma_kernel<<<128, 256, FSM_BYTES>>>();
    combine_kernel<<<1024, 256>>>(out);
}